// round 10
// baseline (speedup 1.0000x reference)
#include <cuda_runtime.h>
#include <cuda_bf16.h>
#include <mma.h>
#include <math.h>

using namespace nvcuda;

// Inputs (metadata order):
// 0 tag_ids[386] i32, 1 word_ids[386] i32, 2 tag_emb[50,128], 3 word_emb[10000,384],
// 4 Wf_ih[2048,512], 5 Wf_hh[2048,512], 6 bf[2048], 7 Wb_ih[2048,512], 8 Wb_hh[2048,512], 9 bb[2048],
// 10 W1[1024,1024], 11 b1[1024], 12 W2[1024,128], 13 b2[128],
// 14 V1[1024,1024], 15 c1[1024], 16 V2[1024,1], 17 c2[1]
// Output: [73920, 129] f32

#define TT 386
#define HH 512
#define G4 2048
#define NP1 385
#define OUTC 129
#define LSTM_BD 32   // blocks per direction

// ------------- device scratch (no mallocs allowed) -------------
__device__ float d_x[TT * 512];
__device__ float d_gx[2][TT * G4];
__device__ float d_states[2][TT * HH];   // [0]=fwd[t], [1]=bwd[t] (original time index)
__device__ unsigned int d_flag[2][LSTM_BD];
__device__ float d_E[NP1 * 1024];
__device__ float d_F[NP1 * 1024];
__device__ __nv_bfloat16 d_W2hi[1024 * 128];
__device__ __nv_bfloat16 d_W2lo[1024 * 128];

static __device__ __forceinline__ float4 f4sub(float4 a, float4 b) {
    return make_float4(a.x - b.x, a.y - b.y, a.z - b.z, a.w - b.w);
}

static __device__ __forceinline__ float fast_sigmoid(float x) {
    return __fdividef(1.f, 1.f + __expf(-x));
}
static __device__ __forceinline__ float fast_tanh(float x) {
    x = fminf(fmaxf(x, -15.f), 15.f);
    float e = __expf(-2.f * x);
    return __fdividef(1.f - e, 1.f + e);
}

static __device__ __forceinline__ unsigned int ld_acquire(const unsigned int* p) {
    unsigned int v;
    asm volatile("ld.acquire.gpu.global.u32 %0, [%1];" : "=r"(v) : "l"(p) : "memory");
    return v;
}
static __device__ __forceinline__ void st_release(unsigned int* p, unsigned int v) {
    asm volatile("st.release.gpu.global.u32 [%0], %1;" :: "l"(p), "r"(v) : "memory");
}

// packed f32x2 helpers (Blackwell sm_100a)
static __device__ __forceinline__ unsigned long long pack2(float lo, float hi) {
    unsigned long long r;
    asm("mov.b64 %0, {%1, %2};" : "=l"(r) : "f"(lo), "f"(hi));
    return r;
}
static __device__ __forceinline__ void unpack2(unsigned long long v, float& lo, float& hi) {
    asm("mov.b64 {%0, %1}, %2;" : "=f"(lo), "=f"(hi) : "l"(v));
}
static __device__ __forceinline__ unsigned long long fma2(unsigned long long a, unsigned long long b,
                                                          unsigned long long c) {
    unsigned long long d;
    asm("fma.rn.f32x2 %0, %1, %2, %3;" : "=l"(d) : "l"(a), "l"(b), "l"(c));
    return d;
}

// ---------------- embed: x[t] = [tag_emb[tag], word_emb[word]]; also reset flags ----------------
__global__ void embed_kernel(const int* __restrict__ tag_ids, const int* __restrict__ word_ids,
                             const float* __restrict__ tag_emb, const float* __restrict__ word_emb) {
    int t = blockIdx.x;
    int tid = threadIdx.x;  // 128 threads: 128 float4 = 512 floats
    if (t == 0 && tid < 2 * LSTM_BD) ((unsigned int*)d_flag)[tid] = 0u;
    int tg = tag_ids[t], wd = word_ids[t];
    float4 v;
    if (tid < 32) v = ((const float4*)(tag_emb + (size_t)tg * 128))[tid];
    else          v = ((const float4*)(word_emb + (size_t)wd * 384))[tid - 32];
    ((float4*)(d_x + (size_t)t * 512))[tid] = v;
}

// ---------------- W2 bf16 hi/lo split ----------------
__global__ void w2split_kernel(const float* __restrict__ W2) {
    int i = blockIdx.x * blockDim.x + threadIdx.x;
    if (i < 1024 * 128) {
        float w = W2[i];
        __nv_bfloat16 hi = __float2bfloat16(w);
        d_W2hi[i] = hi;
        d_W2lo[i] = __float2bfloat16(w - __bfloat162float(hi));
    }
}

// ---------------- gx = x @ W_ih^T + b,  both directions ----------------
__global__ __launch_bounds__(256) void gx_kernel(const float* __restrict__ Wf, const float* __restrict__ bfv,
                                                 const float* __restrict__ Wb, const float* __restrict__ bbv) {
    int dir = blockIdx.z;
    const float* W = dir ? Wb : Wf;
    const float* bias = dir ? bbv : bfv;
    int j0 = blockIdx.x * 64;
    int t0 = blockIdx.y * 32;
    __shared__ float xs[32][65];
    __shared__ float ws[64][65];
    int tid = threadIdx.x;
    int tt = tid >> 5, tj = tid & 31;
    float acc[4][2] = {};
    for (int kc = 0; kc < 8; kc++) {
#pragma unroll
        for (int i = 0; i < 2; i++) {
            int fi = tid + i * 256;
            int row = fi >> 4, q = fi & 15;
            float4 v = make_float4(0.f, 0.f, 0.f, 0.f);
            if (t0 + row < TT) v = *(const float4*)&d_x[(size_t)(t0 + row) * 512 + kc * 64 + q * 4];
            xs[row][q * 4 + 0] = v.x; xs[row][q * 4 + 1] = v.y;
            xs[row][q * 4 + 2] = v.z; xs[row][q * 4 + 3] = v.w;
        }
#pragma unroll
        for (int i = 0; i < 4; i++) {
            int fi = tid + i * 256;
            int j = fi >> 4, q = fi & 15;
            float4 v = *(const float4*)&W[(size_t)(j0 + j) * 512 + kc * 64 + q * 4];
            ws[j][q * 4 + 0] = v.x; ws[j][q * 4 + 1] = v.y;
            ws[j][q * 4 + 2] = v.z; ws[j][q * 4 + 3] = v.w;
        }
        __syncthreads();
#pragma unroll 8
        for (int kk = 0; kk < 64; kk++) {
            float b0 = ws[tj * 2 + 0][kk];
            float b1 = ws[tj * 2 + 1][kk];
#pragma unroll
            for (int i = 0; i < 4; i++) {
                float a = xs[tt * 4 + i][kk];
                acc[i][0] = fmaf(a, b0, acc[i][0]);
                acc[i][1] = fmaf(a, b1, acc[i][1]);
            }
        }
        __syncthreads();
    }
    float bj0 = bias[j0 + tj * 2 + 0];
    float bj1 = bias[j0 + tj * 2 + 1];
#pragma unroll
    for (int i = 0; i < 4; i++) {
        int t = t0 + tt * 4 + i;
        if (t < TT) {
            d_gx[dir][(size_t)t * G4 + j0 + tj * 2 + 0] = acc[i][0] + bj0;
            d_gx[dir][(size_t)t * G4 + j0 + tj * 2 + 1] = acc[i][1] + bj1;
        }
    }
}

// ---------------- persistent bidirectional LSTM (R8-proven skeleton, slimmer reduction) ----------------
// 64 blocks: [0,32) forward, [32,64) backward. 256 threads, 8 warps.
// Block bi owns h indices [bi*16, bi*16+16) = 64 Whh rows, in packed f32x2 regs.
// Sync per step (FROZEN, proven): warp 0 acquire-polls the 32 per-block flags,
// B1 __syncthreads releases the block; compute; B2 __syncthreads; tid0
// release-stores its flag.
// Reduction: round1 (xor16) folds 8 accs to 4 (low half keeps rows p=0..3,
// high half rows p=4..7), rounds 2-5 reduce 4 values. Gate lanes: 0 and 16.
__global__ __launch_bounds__(256, 1) void lstm_kernel(const float* __restrict__ Wf_hh,
                                                      const float* __restrict__ Wb_hh) {
    int dir = blockIdx.x >> 5;
    int bi = blockIdx.x & 31;
    const float* Whh = dir ? Wb_hh : Wf_hh;
    int tid = threadIdx.x;
    int w = tid >> 5, s = tid & 31;

    // Whh slice packed into f32x2 registers: rows rr=w*8+p, k = j*128 + s*4
    unsigned long long wp[8][4][2];
#pragma unroll
    for (int p = 0; p < 8; p++) {
        int rr = w * 8 + p;
        int q = rr >> 2, g = rr & 3;
        int grow = g * 512 + bi * 16 + q;
#pragma unroll
        for (int j = 0; j < 4; j++) {
            float4 wv = *(const float4*)&Whh[(size_t)grow * 512 + j * 128 + s * 4];
            wp[p][j][0] = pack2(wv.x, wv.y);
            wp[p][j][1] = pack2(wv.z, wv.w);
        }
    }
    float c_reg = 0.f;
    unsigned int* flags = &d_flag[dir][0];

    for (int t = 0; t < TT; t++) {
        int ti = dir ? (TT - 1 - t) : t;

        // gx for this step: lane p<8 of warp w owns row rr=w*8+p
        float gxv = 0.f;
        if (s < 8) {
            int q = 2 * w + (s >> 2), g = s & 3;
            gxv = __ldcg(&d_gx[dir][(size_t)ti * G4 + g * 512 + bi * 16 + q]);
        }

        if (t > 0) {
            if (w == 0) {
                unsigned int target = (unsigned)t;
                unsigned int f;
                int spins = 0;
                do {
                    f = ld_acquire(&flags[s]);
                } while (__any_sync(0xffffffffu, f < target) && ++spins < 100000);
            }
            __syncthreads();   // B1
        }

        float4 hv[4];
        if (t == 0) {
#pragma unroll
            for (int j = 0; j < 4; j++) hv[j] = make_float4(0.f, 0.f, 0.f, 0.f);
        } else {
            int tprev = dir ? (ti + 1) : (ti - 1);
#pragma unroll
            for (int j = 0; j < 4; j++)
                hv[j] = __ldcg((const float4*)&d_states[dir][(size_t)tprev * HH + j * 128 + s * 4]);
        }

        unsigned long long acc2[8] = {0ull, 0ull, 0ull, 0ull, 0ull, 0ull, 0ull, 0ull};
#pragma unroll
        for (int j = 0; j < 4; j++) {
            unsigned long long hp0 = pack2(hv[j].x, hv[j].y);
            unsigned long long hp1 = pack2(hv[j].z, hv[j].w);
#pragma unroll
            for (int p = 0; p < 8; p++) {
                acc2[p] = fma2(hp0, wp[p][j][0], acc2[p]);
                acc2[p] = fma2(hp1, wp[p][j][1], acc2[p]);
            }
        }
        float acc[8];
#pragma unroll
        for (int p = 0; p < 8; p++) {
            float lo, hi;
            unpack2(acc2[p], lo, hi);
            acc[p] = lo + hi;
        }
        // Round 1 (xor16): fold 8 -> 4. Low half tracks rows p=0..3 (q=2w),
        // high half rows p=4..7 (q=2w+1).
        float b4[4];
#pragma unroll
        for (int q = 0; q < 4; q++) {
            float t0 = __shfl_xor_sync(0xffffffffu, acc[q], 16);
            float t1 = __shfl_xor_sync(0xffffffffu, acc[q + 4], 16);
            b4[q] = (s < 16) ? (acc[q] + t0) : (acc[q + 4] + t1);
        }
#pragma unroll
        for (int off = 8; off >= 1; off >>= 1) {
#pragma unroll
            for (int q = 0; q < 4; q++)
                b4[q] += __shfl_xor_sync(0xffffffffu, b4[q], off);
        }
        // gather gx to the gate lanes (0 -> rows p=0..3 at lanes 0..3;
        // 16 -> rows p=4..7 at lanes 4..7)
        int gbase = (s >= 16) ? 4 : 0;
        float gx0 = __shfl_sync(0xffffffffu, gxv, gbase + 0);
        float gx1 = __shfl_sync(0xffffffffu, gxv, gbase + 1);
        float gx2 = __shfl_sync(0xffffffffu, gxv, gbase + 2);
        float gx3 = __shfl_sync(0xffffffffu, gxv, gbase + 3);

        if (s == 0 || s == 16) {
            float gi = b4[0] + gx0;
            float gf = b4[1] + gx1;
            float gg = b4[2] + gx2;
            float go = b4[3] + gx3;
            float iv = fast_sigmoid(gi);
            float fv = fast_sigmoid(gf);
            float ov = fast_sigmoid(go);
            float c = fv * c_reg + iv * fast_tanh(gg);
            float h = ov * fast_tanh(c);
            c_reg = c;
            int q = 2 * w + (s >> 4);
            __stcg(&d_states[dir][(size_t)ti * HH + bi * 16 + q], h);
        }
        __syncthreads();       // B2: all warps' h stores done before release
        if (tid == 0) st_release(&flags[bi], (unsigned)(t + 1));
    }
}

// ---------------- E/F precompute: 64x64 tile, 4x4 register tile ----------------
// E[t] = fwd[t] @ W1[0:512] - bwd[t+1] @ W1[512:1024]; F likewise with V1.
// grid (16 jtiles of 64, 7 ttiles of 64, 2 which), 256 threads (16 tr x 16 tc).
__global__ __launch_bounds__(256) void e_kernel(const float* __restrict__ W1,
                                                const float* __restrict__ V1) {
    int which = blockIdx.z;
    const float* B = which ? V1 : W1;
    float* outp = which ? d_F : d_E;
    int j0 = blockIdx.x * 64;
    int t0 = blockIdx.y * 64;
    __shared__ float as_[64][65];
    __shared__ float ws[64][68];   // row stride 272B = 17*16 -> float4-aligned
    int tid = threadIdx.x;
    int tr = tid >> 4, tc = tid & 15;
    float acc[4][4] = {};
    for (int kc = 0; kc < 16; kc++) {
        int half = kc >> 3;            // 0: fwd (+), 1: bwd[t+1] (-)
        int koff = (kc & 7) * 64;
#pragma unroll
        for (int i = 0; i < 4; i++) {
            int fi = tid + i * 256;    // 1024 float4: 64 rows x 16 quads of A
            int row = fi >> 4, q = fi & 15;
            float4 v = make_float4(0.f, 0.f, 0.f, 0.f);
            int trow = t0 + row;
            if (trow < NP1) {
                const float* src = half ? &d_states[1][(size_t)(trow + 1) * HH + koff + q * 4]
                                        : &d_states[0][(size_t)trow * HH + koff + q * 4];
                v = *(const float4*)src;
                if (half) { v.x = -v.x; v.y = -v.y; v.z = -v.z; v.w = -v.w; }
            }
            as_[row][q * 4 + 0] = v.x; as_[row][q * 4 + 1] = v.y;
            as_[row][q * 4 + 2] = v.z; as_[row][q * 4 + 3] = v.w;
        }
#pragma unroll
        for (int i = 0; i < 4; i++) {
            int fi = tid + i * 256;    // 1024 float4: 64 k-rows x 16 quads of B
            int k = fi >> 4, q = fi & 15;
            float4 v = *(const float4*)&B[(size_t)(half * 512 + koff + k) * 1024 + j0 + q * 4];
            *(float4*)&ws[k][q * 4] = v;
        }
        __syncthreads();
#pragma unroll 8
        for (int kk = 0; kk < 64; kk++) {
            float4 bv = *(const float4*)&ws[kk][tc * 4];
#pragma unroll
            for (int i = 0; i < 4; i++) {
                float a = as_[tr * 4 + i][kk];
                acc[i][0] = fmaf(a, bv.x, acc[i][0]);
                acc[i][1] = fmaf(a, bv.y, acc[i][1]);
                acc[i][2] = fmaf(a, bv.z, acc[i][2]);
                acc[i][3] = fmaf(a, bv.w, acc[i][3]);
            }
        }
        __syncthreads();
    }
#pragma unroll
    for (int i = 0; i < 4; i++) {
        int t = t0 + tr * 4 + i;
        if (t < NP1) {
            float4 o = make_float4(acc[i][0], acc[i][1], acc[i][2], acc[i][3]);
            *(float4*)&outp[(size_t)t * 1024 + j0 + tc * 4] = o;
        }
    }
}

// ---------------- span kernel: tensor cores (bf16 hi/lo split, R5-proven) ----------------
#define TILE_R 128
#define SP_BASE1 0
#define SP_BASEV 4096
#define SP_V2    8192
#define SP_B2    12288
#define SP_AHI   12800
#define SP_ALO   31232
#define SP_BHI   49664
#define SP_BLO   67072
#define SP_TOTAL 84480
#define SP_STAGE SP_AHI

__global__ __launch_bounds__(512) void span_kernel(const float* __restrict__ b1,
                                                   const float* __restrict__ b2,
                                                   const float* __restrict__ c1,
                                                   const float* __restrict__ V2,
                                                   const float* __restrict__ c2,
                                                   float* __restrict__ out) {
    int l = blockIdx.y;
    int r0 = l + 1 + blockIdx.x * TILE_R;
    if (r0 > 384) return;
    int nr = min(TILE_R, 385 - r0);

    extern __shared__ char smem[];
    float* base1 = (float*)(smem + SP_BASE1);
    float* baseV = (float*)(smem + SP_BASEV);
    float* v2s   = (float*)(smem + SP_V2);
    float* b2s   = (float*)(smem + SP_B2);
    __nv_bfloat16* Ahi = (__nv_bfloat16*)(smem + SP_AHI);   // [128][72]
    __nv_bfloat16* Alo = (__nv_bfloat16*)(smem + SP_ALO);
    __nv_bfloat16* Bhi = (__nv_bfloat16*)(smem + SP_BHI);   // [64][136]
    __nv_bfloat16* Blo = (__nv_bfloat16*)(smem + SP_BLO);
    float* stage = (float*)(smem + SP_STAGE);               // [128][68]

    int tid = threadIdx.x;
    int wid = tid >> 5;
    int mw = wid & 3, nw = wid >> 2;

    if (tid < 256) {
        ((float4*)base1)[tid] = f4sub(((const float4*)b1)[tid], ((const float4*)&d_E[(size_t)l * 1024])[tid]);
        ((float4*)baseV)[tid] = f4sub(((const float4*)c1)[tid], ((const float4*)&d_F[(size_t)l * 1024])[tid]);
        ((float4*)v2s)[tid] = ((const float4*)V2)[tid];
        if (tid < 32) ((float4*)b2s)[tid] = ((const float4*)b2)[tid];
    }

    wmma::fragment<wmma::accumulator, 16, 16, 16, float> acc[2][2];
#pragma unroll
    for (int i = 0; i < 2; i++)
#pragma unroll
        for (int j = 0; j < 2; j++)
            wmma::fill_fragment(acc[i][j], 0.0f);

    float sacc[4] = {0.f, 0.f, 0.f, 0.f};
    long sbase = (long)l * 384 - (long)l * (l - 1) / 2 + (r0 - l - 1);
    __syncthreads();

    for (int kc = 0; kc < 16; kc++) {
#pragma unroll
        for (int i = 0; i < 4; i++) {
            int fi = tid + i * 512;
            int row = fi >> 4, q = fi & 15;
            int k = kc * 64 + q * 4;
            float4 e = make_float4(0.f, 0.f, 0.f, 0.f), f = e;
            if (row < nr) {
                e = *(const float4*)&d_E[(size_t)(r0 + row) * 1024 + k];
                f = *(const float4*)&d_F[(size_t)(r0 + row) * 1024 + k];
            }
            float4 bb = *(const float4*)&base1[k];
            float h0 = fmaxf(e.x + bb.x, 0.f), h1v = fmaxf(e.y + bb.y, 0.f);
            float h2v = fmaxf(e.z + bb.z, 0.f), h3 = fmaxf(e.w + bb.w, 0.f);
            __nv_bfloat16 a0 = __float2bfloat16(h0), a1 = __float2bfloat16(h1v);
            __nv_bfloat16 a2 = __float2bfloat16(h2v), a3 = __float2bfloat16(h3);
            int ab = row * 72 + q * 4;
            Ahi[ab + 0] = a0; Ahi[ab + 1] = a1; Ahi[ab + 2] = a2; Ahi[ab + 3] = a3;
            Alo[ab + 0] = __float2bfloat16(h0 - __bfloat162float(a0));
            Alo[ab + 1] = __float2bfloat16(h1v - __bfloat162float(a1));
            Alo[ab + 2] = __float2bfloat16(h2v - __bfloat162float(a2));
            Alo[ab + 3] = __float2bfloat16(h3 - __bfloat162float(a3));
            float4 bv = *(const float4*)&baseV[k];
            float4 vv = *(const float4*)&v2s[k];
            float t0 = fmaxf(f.x + bv.x, 0.f) * vv.x + fmaxf(f.y + bv.y, 0.f) * vv.y;
            float t1 = fmaxf(f.z + bv.z, 0.f) * vv.z + fmaxf(f.w + bv.w, 0.f) * vv.w;
            sacc[i] += t0 + t1;
        }
#pragma unroll
        for (int j = 0; j < 2; j++) {
            int idx = tid + j * 512;
            int k = idx >> 4, c = idx & 15;
            const int4* srch = (const int4*)&d_W2hi[(size_t)(kc * 64 + k) * 128 + c * 8];
            const int4* srcl = (const int4*)&d_W2lo[(size_t)(kc * 64 + k) * 128 + c * 8];
            *(int4*)&Bhi[k * 136 + c * 8] = *srch;
            *(int4*)&Blo[k * 136 + c * 8] = *srcl;
        }
        __syncthreads();

#pragma unroll
        for (int kk = 0; kk < 4; kk++) {
            wmma::fragment<wmma::matrix_a, 16, 16, 16, __nv_bfloat16, wmma::row_major> ah[2], al[2];
            wmma::fragment<wmma::matrix_b, 16, 16, 16, __nv_bfloat16, wmma::row_major> bh[2], bl[2];
#pragma unroll
            for (int i = 0; i < 2; i++) {
                wmma::load_matrix_sync(ah[i], &Ahi[(mw * 32 + i * 16) * 72 + kk * 16], 72);
                wmma::load_matrix_sync(al[i], &Alo[(mw * 32 + i * 16) * 72 + kk * 16], 72);
            }
#pragma unroll
            for (int j = 0; j < 2; j++) {
                wmma::load_matrix_sync(bh[j], &Bhi[(kk * 16) * 136 + nw * 32 + j * 16], 136);
                wmma::load_matrix_sync(bl[j], &Blo[(kk * 16) * 136 + nw * 32 + j * 16], 136);
            }
#pragma unroll
            for (int i = 0; i < 2; i++)
#pragma unroll
                for (int j = 0; j < 2; j++) {
                    wmma::mma_sync(acc[i][j], ah[i], bh[j], acc[i][j]);
                    wmma::mma_sync(acc[i][j], ah[i], bl[j], acc[i][j]);
                    wmma::mma_sync(acc[i][j], al[i], bh[j], acc[i][j]);
                }
        }
        __syncthreads();
    }

#pragma unroll
    for (int off = 1; off < 16; off <<= 1) {
#pragma unroll
        for (int i = 0; i < 4; i++)
            sacc[i] += __shfl_xor_sync(0xffffffffu, sacc[i], off);
    }
    float c2v = c2[0];
    if ((tid & 15) == 0) {
#pragma unroll
        for (int i = 0; i < 4; i++) {
            int row = (tid >> 4) + i * 32;
            if (row < nr) out[(sbase + row) * (long)OUTC + 128] = sacc[i] + c2v;
        }
    }

#pragma unroll
    for (int p = 0; p < 2; p++) {
        if ((nw >> 1) == p) {
#pragma unroll
            for (int i = 0; i < 2; i++)
#pragma unroll
                for (int j = 0; j < 2; j++)
                    wmma::store_matrix_sync(&stage[(mw * 32 + i * 16) * 68 + (nw & 1) * 32 + j * 16],
                                            acc[i][j], 68, wmma::mem_row_major);
        }
        __syncthreads();
#pragma unroll
        for (int j = 0; j < 16; j++) {
            int idx = tid + j * 512;
            int row = idx >> 6, c = idx & 63;
            if (row < nr)
                out[(sbase + row) * (long)OUTC + p * 64 + c] = stage[row * 68 + c] + b2s[p * 64 + c];
        }
        __syncthreads();
    }
}

// ---------------- launch ----------------
extern "C" void kernel_launch(void* const* d_in, const int* in_sizes, int n_in,
                              void* d_out, int out_size) {
    const int* tag_ids = (const int*)d_in[0];
    const int* word_ids = (const int*)d_in[1];
    const float* tag_emb = (const float*)d_in[2];
    const float* word_emb = (const float*)d_in[3];
    const float* Wf_ih = (const float*)d_in[4];
    const float* Wf_hh = (const float*)d_in[5];
    const float* bf = (const float*)d_in[6];
    const float* Wb_ih = (const float*)d_in[7];
    const float* Wb_hh = (const float*)d_in[8];
    const float* bb = (const float*)d_in[9];
    const float* W1 = (const float*)d_in[10];
    const float* b1 = (const float*)d_in[11];
    const float* W2 = (const float*)d_in[12];
    const float* b2 = (const float*)d_in[13];
    const float* V1 = (const float*)d_in[14];
    const float* c1 = (const float*)d_in[15];
    const float* V2 = (const float*)d_in[16];
    const float* c2 = (const float*)d_in[17];
    float* out = (float*)d_out;

    cudaFuncSetAttribute(span_kernel, cudaFuncAttributeMaxDynamicSharedMemorySize, SP_TOTAL);

    embed_kernel<<<TT, 128>>>(tag_ids, word_ids, tag_emb, word_emb);
    w2split_kernel<<<512, 256>>>(W2);

    dim3 ggx(32, 13, 2);
    gx_kernel<<<ggx, 256>>>(Wf_ih, bf, Wb_ih, bb);

    lstm_kernel<<<64, 256>>>(Wf_hh, Wb_hh);

    dim3 ge(16, 7, 2);
    e_kernel<<<ge, 256>>>(W1, V1);

    dim3 gs(3, 384);
    span_kernel<<<gs, 512, SP_TOTAL>>>(b1, b2, c1, V2, c2, out);

    (void)in_sizes; (void)n_in; (void)out_size;
}